// round 14
// baseline (speedup 1.0000x reference)
#include <cuda_runtime.h>
#include <cuda_bf16.h>
#include <cstdint>

// ---------------- arch-feature gate ----------------
#if defined(__CUDA_ARCH_FEAT_SM103_ALL) || defined(__CUDA_ARCH_FEAT_SM100_ALL) || \
    defined(__CUDA_ARCH_FEAT_SM101_ALL) ||                                        \
    (defined(__CUDA_ARCH_SPECIFIC__) && (__CUDA_ARCH_SPECIFIC__ >= 1000))
#define HAS_TCGEN05 1
#else
#define HAS_TCGEN05 0
#endif

// ---------------- problem/tiling ----------------
// out[f, hw] = relu( sum_c W[f,c] * X[c,hw] + b[f] ),  F=C=512, HW=65536.
// 2-CTA cluster cg2 MMA: cluster tile D[hw=256 (128/CTA), f=512 (2 disp N=256,
// B split per CTA)]. A = X^T K-major, converted once chip-wide.
// K=512 in 16 chunks of 32; 3 passes: Ah*Bh + Ah*Bl + Al*Bh (bf16 split).
// R14: NSTAGE=4 with COMMIT EVERY 2 CHUNKS — amortizes the tcgen05 commit
// drain (queue depth ~4-6) that capped tensor duty at ~46%.
#define NCHUNK 16
#define NSTAGE 4
#define NTHREADS 544          // 512 producers (warps 0-15) + MMA warp (16)
#define PRODS 512

// Prepacked W (1 MB): g_WP[ch][rank][disp][fr][128B row = hi bf16 c32 | lo c32],
// f = disp*256 + rank*128 + fr, pre-SW128-swizzled by fr%8.
__device__ __align__(128) unsigned char g_WP[16ull * 512ull * 128ull];

// ---------------- smem layout ----------------
// 0: tmem ptr | 16+16s: FULL[s] s<4 | 96+16p: EMPTY[p] p<2 | 128+16s: PEER[s]
// | 192: DONE | 2048: bias (512 f) | 4096 + s*49152: stage s {A 16K | B 32K}
// | 200704: Xs fp32 staging [32 c][128 hw] 16KB (single buffer)
#define STAGE0   4096
#define STAGE_SZ 49152
#define A_OFF    0
#define B_OFF    16384
#define XS_OFF   (STAGE0 + NSTAGE * STAGE_SZ)     // 200704
#define BIAS_OFF 2048
#define SMEM_TOTAL (XS_OFF + 16384)               // 217088
#define MBAR_FULL(s)  (16u + 16u * (s))
#define MBAR_EMPTY(p) (96u + 16u * (p))
#define MBAR_PEER(s)  (128u + 16u * (s))
#define MBAR_DONE     192u

// idesc kind::f16 cg2 (proven): dtype=F32(b4), atype=BF16(b7), btype=BF16(b10),
// N=256 -> 32<<17, M_TOTAL=256 -> 16<<24
static constexpr unsigned IDESC =
    (1u << 4) | (1u << 7) | (1u << 10) | (32u << 17) | (16u << 24);

__device__ __forceinline__ uint32_t smem_u32(const void* p) {
    uint32_t a;
    asm("{ .reg .u64 t; cvta.to.shared.u64 t, %1; cvt.u32.u64 %0, t; }" : "=r"(a) : "l"(p));
    return a;
}
__device__ __forceinline__ uint32_t pack_lo_bf16x2(float x0, float x1) {
    __nv_bfloat162 p = __floats2bfloat162_rn(x0, x1);
    return *reinterpret_cast<uint32_t*>(&p);
}

#if HAS_TCGEN05
__device__ __forceinline__ uint32_t ctarank() {
    uint32_t r;
    asm("mov.u32 %0, %%cluster_ctarank;" : "=r"(r));
    return r;
}
__device__ __forceinline__ void cluster_sync() {
    asm volatile("barrier.cluster.arrive.aligned;" ::: "memory");
    asm volatile("barrier.cluster.wait.aligned;" ::: "memory");
}
__device__ __forceinline__ void mbar_init(uint32_t a, uint32_t cnt) {
    asm volatile("mbarrier.init.shared.b64 [%0], %1;" :: "r"(a), "r"(cnt) : "memory");
}
__device__ __forceinline__ void mbar_arrive(uint32_t a) {
    asm volatile("mbarrier.arrive.shared.b64 _, [%0];" :: "r"(a) : "memory");
}
__device__ __forceinline__ void mbar_arrive_rank0(uint32_t a) {
    asm volatile(
        "{\n\t.reg .b32 rem;\n\t"
        "mapa.shared::cluster.u32 rem, %0, 0;\n\t"
        "mbarrier.arrive.shared::cluster.b64 _, [rem];\n\t}"
        :: "r"(a) : "memory");
}
__device__ __forceinline__ void mbar_wait(uint32_t a, uint32_t parity) {
    asm volatile(
        "{\n\t.reg .pred P;\n\t"
        "WL%=:\n\t"
        "mbarrier.try_wait.parity.acquire.cta.shared::cta.b64 P, [%0], %1, 0x989680;\n\t"
        "@!P bra WL%=;\n\t}"
        :: "r"(a), "r"(parity) : "memory");
}
__device__ __forceinline__ void expect_tx(uint32_t a, uint32_t bytes) {
    asm volatile("mbarrier.arrive.expect_tx.shared.b64 _, [%0], %1;"
                 :: "r"(a), "r"(bytes) : "memory");
}
__device__ __forceinline__ void bulk_g2s(uint32_t dst, uint64_t gsrc,
                                         uint32_t bytes, uint32_t mbar) {
    asm volatile(
        "cp.async.bulk.shared::cluster.global.mbarrier::complete_tx::bytes "
        "[%0], [%1], %2, [%3];"
        :: "r"(dst), "l"(gsrc), "r"(bytes), "r"(mbar) : "memory");
}
__device__ __forceinline__ uint64_t sw128_desc_k(uint32_t addr) {
    return (2ull << 61) | (1ull << 46) | (64ull << 32) | (1ull << 16) |
           ((uint64_t)(addr >> 4) & 0x3FFFull);
}
__device__ __forceinline__ void mma_ss_cg2(uint32_t d, uint64_t ad, uint64_t bd,
                                           uint32_t en) {
    asm volatile(
        "{\n\t.reg .pred p;\n\tsetp.ne.u32 p, %5, 0;\n\t"
        "tcgen05.mma.cta_group::2.kind::f16 [%0], %1, %2, %3, "
        "{%4, %4, %4, %4, %4, %4, %4, %4}, p;\n\t}"
        :: "r"(d), "l"(ad), "l"(bd), "r"(IDESC), "r"(0u), "r"(en) : "memory");
}
__device__ __forceinline__ void mma_commit_mc2(uint32_t mbar) {
    asm volatile(
        "tcgen05.commit.cta_group::2.mbarrier::arrive::one.shared::cluster"
        ".multicast::cluster.b64 [%0], %1;"
        :: "r"(mbar), "h"((uint16_t)0x3) : "memory");
}
__device__ __forceinline__ void ldtm_x32(uint32_t* r, uint32_t a) {
    asm volatile(
        "tcgen05.ld.sync.aligned.32x32b.x32.b32 "
        "{%0, %1, %2, %3, %4, %5, %6, %7, "
        " %8, %9, %10, %11, %12, %13, %14, %15, "
        " %16, %17, %18, %19, %20, %21, %22, %23, "
        " %24, %25, %26, %27, %28, %29, %30, %31}, [%32];"
        : "=r"(r[0]),  "=r"(r[1]),  "=r"(r[2]),  "=r"(r[3]),
          "=r"(r[4]),  "=r"(r[5]),  "=r"(r[6]),  "=r"(r[7]),
          "=r"(r[8]),  "=r"(r[9]),  "=r"(r[10]), "=r"(r[11]),
          "=r"(r[12]), "=r"(r[13]), "=r"(r[14]), "=r"(r[15]),
          "=r"(r[16]), "=r"(r[17]), "=r"(r[18]), "=r"(r[19]),
          "=r"(r[20]), "=r"(r[21]), "=r"(r[22]), "=r"(r[23]),
          "=r"(r[24]), "=r"(r[25]), "=r"(r[26]), "=r"(r[27]),
          "=r"(r[28]), "=r"(r[29]), "=r"(r[30]), "=r"(r[31])
        : "r"(a));
}
#endif  // HAS_TCGEN05

// =====================================================================
// W prepass (~6us): g_WP[ch][rank][disp][fr][128B].
// =====================================================================
__global__ void __launch_bounds__(256) wprep_kernel(const float* __restrict__ W) {
    int item = blockIdx.x * 256 + threadIdx.x;   // 8192 items
    int f = item >> 4;
    int ch = item & 15;
    int disp = f >> 8;
    int rank = (f >> 7) & 1;
    int fr = f & 127;
    const float* wr = W + (size_t)f * 512 + ch * 32;
    float v[32];
    #pragma unroll
    for (int i = 0; i < 8; i++)
        *reinterpret_cast<float4*>(v + 4 * i) =
            *reinterpret_cast<const float4*>(wr + 4 * i);
    uint32_t hi[16], lo[16];
    #pragma unroll
    for (int p = 0; p < 16; p++) {
        uint32_t u0 = __float_as_uint(v[2 * p]), u1 = __float_as_uint(v[2 * p + 1]);
        hi[p] = __byte_perm(u0, u1, 0x7632);
        lo[p] = pack_lo_bf16x2(v[2 * p]     - __uint_as_float(u0 & 0xFFFF0000u),
                               v[2 * p + 1] - __uint_as_float(u1 & 0xFFFF0000u));
    }
    unsigned char* row = g_WP +
        ((((size_t)ch * 2 + rank) * 2 + disp) * 128 + fr) * 128;
    int r7 = fr & 7;
    #pragma unroll
    for (int j = 0; j < 4; j++)
        *reinterpret_cast<uint4*>(row + ((j ^ r7) * 16)) =
            make_uint4(hi[4 * j], hi[4 * j + 1], hi[4 * j + 2], hi[4 * j + 3]);
    #pragma unroll
    for (int j = 0; j < 4; j++)
        *reinterpret_cast<uint4*>(row + (((j + 4) ^ r7) * 16)) =
            make_uint4(lo[4 * j], lo[4 * j + 1], lo[4 * j + 2], lo[4 * j + 3]);
}

// =====================================================================
// Main GEMM. grid=512 (clusters of 2), 544 threads.
// =====================================================================
__global__ void __launch_bounds__(NTHREADS, 1) __cluster_dims__(2, 1, 1)
spconv_kernel(const float* __restrict__ X, const float* __restrict__ W,
              const float* __restrict__ bias, float* __restrict__ out)
{
    extern __shared__ char smem[];
    const int tid = threadIdx.x;

#if HAS_TCGEN05
    const uint32_t sb = smem_u32(smem);
    const int wid = tid >> 5;
    const int lane = tid & 31;
    const uint32_t rank = ctarank();
    const int hw0 = (blockIdx.x >> 1) * 256;
    const int hwA0 = hw0 + (int)rank * 128;      // this CTA's A rows

    if (wid == 0) {
        asm volatile("tcgen05.alloc.cta_group::2.sync.aligned.shared::cta.b32 [%0], %1;"
                     :: "r"(sb), "r"(512u) : "memory");
        asm volatile("tcgen05.relinquish_alloc_permit.cta_group::2.sync.aligned;" ::: "memory");
    }
    if (tid == 0) {
        #pragma unroll
        for (int s = 0; s < NSTAGE; s++) {
            mbar_init(sb + MBAR_FULL(s), PRODS + 1);     // producers + expect_tx
            mbar_init(sb + MBAR_PEER(s), 1);             // rank1 cluster-arrive
        }
        mbar_init(sb + MBAR_EMPTY(0), 1);                // pair commits
        mbar_init(sb + MBAR_EMPTY(1), 1);
        mbar_init(sb + MBAR_DONE, 1);
    }
    if (tid < PRODS)
        reinterpret_cast<float*>(smem + BIAS_OFF)[tid] = bias[tid];
    __syncthreads();
    cluster_sync();                               // barriers visible cluster-wide
    uint32_t tmem;
    asm volatile("ld.shared.b32 %0, [%1];" : "=r"(tmem) : "r"(sb));

    if (tid < PRODS) {
        // ================= producer warps 0-15 =================
        uint64_t wg;
        asm("cvta.to.global.u64 %0, %1;" : "=l"(wg) : "l"((const void*)g_WP));
        wg += (uint64_t)rank * 32768;             // [ch][rank][disp][fr]

        const int xc = tid >> 5;                  // 0..15
        const int xq = tid & 31;                  // 0..31
        const float* xbase = X + hwA0 + xq * 4;
        float* Xs = reinterpret_cast<float*>(smem + XS_OFF);

        float4 pf0 = *reinterpret_cast<const float4*>(xbase + (size_t)xc * 65536);
        float4 pf1 = *reinterpret_cast<const float4*>(xbase + (size_t)(xc + 16) * 65536);

        for (int ch = 0; ch < NCHUNK; ch++) {
            const int s = ch & 3;                 // stage
            const int g = ch >> 2;                // stage-reuse group
            // wait pair-EMPTY: pair = s>>1, parity !(g&1) (fresh pass at g=0)
            mbar_wait(sb + MBAR_EMPTY(s >> 1), (uint32_t)((g & 1) ^ 1));
            char* stg = smem + STAGE0 + s * STAGE_SZ;
            const uint32_t stb = sb + STAGE0 + s * STAGE_SZ;

            if (tid == 0) {
                expect_tx(sb + MBAR_FULL(s), 32768u);
                bulk_g2s(stb + B_OFF, wg + (uint64_t)ch * 65536ull, 32768u,
                         sb + MBAR_FULL(s));
            }

            // guard Xs write-after-read (single buffer): all prior converts done
            asm volatile("bar.sync 2, %0;" :: "r"(PRODS) : "memory");
            *reinterpret_cast<float4*>(&Xs[xc * 128 + xq * 4]) = pf0;
            *reinterpret_cast<float4*>(&Xs[(xc + 16) * 128 + xq * 4]) = pf1;
            asm volatile("bar.sync 1, %0;" :: "r"(PRODS) : "memory");

            if (ch + 1 < NCHUNK) {
                pf0 = *reinterpret_cast<const float4*>(
                    xbase + (size_t)((ch + 1) * 32 + xc) * 65536);
                pf1 = *reinterpret_cast<const float4*>(
                    xbase + (size_t)((ch + 1) * 32 + xc + 16) * 65536);
            }

            // transpose + convert: thread owns (hw row, 8-c octet)
            {
                const int hwl = tid & 127;
                const int h   = tid >> 7;         // c in [8h, 8h+8)
                float v[8];
                #pragma unroll
                for (int j = 0; j < 8; j++)
                    v[j] = Xs[(h * 8 + j) * 128 + hwl];
                uint32_t hi[4], lo[4];
                #pragma unroll
                for (int p = 0; p < 4; p++) {
                    uint32_t u0 = __float_as_uint(v[2 * p]);
                    uint32_t u1 = __float_as_uint(v[2 * p + 1]);
                    hi[p] = __byte_perm(u0, u1, 0x7632);
                    lo[p] = pack_lo_bf16x2(
                        v[2 * p]     - __uint_as_float(u0 & 0xFFFF0000u),
                        v[2 * p + 1] - __uint_as_float(u1 & 0xFFFF0000u));
                }
                unsigned char* row = reinterpret_cast<unsigned char*>(stg + A_OFF) +
                                     (size_t)hwl * 128;
                const int r7 = hwl & 7;
                *reinterpret_cast<uint4*>(row + ((h ^ r7) * 16)) =
                    make_uint4(hi[0], hi[1], hi[2], hi[3]);
                *reinterpret_cast<uint4*>(row + (((4 + h) ^ r7) * 16)) =
                    make_uint4(lo[0], lo[1], lo[2], lo[3]);
            }

            mbar_arrive(sb + MBAR_FULL(s));
        }
    } else if (tid == PRODS) {
        // ================= dedicated MMA thread (warp 16, lane 0) ==========
        for (int ch = 0; ch < NCHUNK; ch++) {
            const int s = ch & 3;
            const uint32_t fpar = (uint32_t)((ch >> 2) & 1);
            const uint32_t stb = sb + STAGE0 + s * STAGE_SZ;
            if (rank == 1) {
                mbar_wait(sb + MBAR_FULL(s), fpar);
                asm volatile("fence.proxy.async.shared::cta;" ::: "memory");
                mbar_arrive_rank0(sb + MBAR_PEER(s));
            } else {
                mbar_wait(sb + MBAR_FULL(s), fpar);
                mbar_wait(sb + MBAR_PEER(s), fpar);
                asm volatile("fence.proxy.async.shared::cta;" ::: "memory");
                uint64_t ad = sw128_desc_k(stb + A_OFF);
                #pragma unroll
                for (int disp = 0; disp < 2; disp++) {   // f halves (N=256)
                    uint64_t bd = sw128_desc_k(stb + B_OFF + disp * 16384);
                    uint32_t d = tmem + disp * 256;
                    #pragma unroll
                    for (int k = 0; k < 2; k++) {        // K=16 steps
                        uint64_t ah = ad + k * 2, al = ad + 4 + k * 2;
                        uint64_t bh = bd + k * 2, bl = bd + 4 + k * 2;
                        mma_ss_cg2(d, ah, bh, (ch == 0 && k == 0) ? 0u : 1u);
                        mma_ss_cg2(d, ah, bl, 1u);
                        mma_ss_cg2(d, al, bh, 1u);
                    }
                }
                if (ch & 1)                              // commit every 2 chunks
                    mma_commit_mc2(sb + MBAR_EMPTY((ch >> 1) & 1));
                if (ch == NCHUNK - 1) mma_commit_mc2(sb + MBAR_DONE);
            }
        }
    }

    // ---- epilogue: producer warps read 128 hw rows x 512 f cols ----
    if (wid < 16) {
        mbar_wait(sb + MBAR_DONE, 0u);
        asm volatile("tcgen05.fence::after_thread_sync;" ::: "memory");

        const float* bias_s = reinterpret_cast<const float*>(smem + BIAS_OFF);
        const int sub = wid & 3;                 // TMEM subpartition
        const int cg  = wid >> 2;                // column group (0..3)
        const int hw  = hwA0 + sub * 32 + lane;
        #pragma unroll
        for (int cb = 0; cb < 4; cb++) {
            uint32_t col = (uint32_t)(cg * 128 + cb * 32);
            uint32_t r[32];
            ldtm_x32(r, tmem + col);
            asm volatile("tcgen05.wait::ld.sync.aligned;" ::: "memory");
            float* op = out + (size_t)col * 65536 + hw;
            #pragma unroll
            for (int j = 0; j < 32; j++) {
                float v = __uint_as_float(r[j]) + bias_s[col + j];
                op[(size_t)j * 65536] = fmaxf(v, 0.0f);
            }
        }
    }

    __syncthreads();
    cluster_sync();                               // both CTAs done reading TMEM
    if (wid == 0) {
        asm volatile("tcgen05.dealloc.cta_group::2.sync.aligned.b32 %0, %1;"
                     :: "r"(tmem), "r"(512u));
    }
    cluster_sync();

#else
    // ========= FFMA fallback (plain pass; never executes on GB300) =========
    if (tid < 512) {
        float* Xsf = reinterpret_cast<float*>(smem);            // [32][128]
        float* Wsf = reinterpret_cast<float*>(smem + 16384);    // [512][32]
        const int hw0f = (int)blockIdx.x * 128;
        const int tx = tid & 15, ty = tid >> 4;
        const int hw_l = tx * 8, f_l = ty * 16;
        float acc[16][8];
        #pragma unroll
        for (int i = 0; i < 16; i++)
            #pragma unroll
            for (int j = 0; j < 8; j++) acc[i][j] = 0.0f;
        for (int ch = 0; ch < 16; ch++) {
            const int c0 = ch * 32;
            #pragma unroll
            for (int i = 0; i < 2; i++) {
                int l = tid + 512 * i, row = l >> 5, c4 = l & 31;
                *reinterpret_cast<float4*>(&Xsf[row * 128 + c4 * 4]) =
                    *reinterpret_cast<const float4*>(
                        &X[(size_t)(c0 + row) * 65536 + hw0f + c4 * 4]);
            }
            #pragma unroll
            for (int i = 0; i < 8; i++) {
                int l = tid + 512 * i, row = l >> 3, c4 = l & 7;
                *reinterpret_cast<float4*>(&Wsf[row * 32 + c4 * 4]) =
                    *reinterpret_cast<const float4*>(
                        &W[(size_t)row * 512 + c0 + c4 * 4]);
            }
            __syncthreads();
            #pragma unroll 4
            for (int c = 0; c < 32; c++) {
                float xv[8];
                *reinterpret_cast<float4*>(xv) =
                    *reinterpret_cast<float4*>(&Xsf[c * 128 + hw_l]);
                *reinterpret_cast<float4*>(xv + 4) =
                    *reinterpret_cast<float4*>(&Xsf[c * 128 + hw_l + 4]);
                #pragma unroll
                for (int i = 0; i < 16; i++) {
                    float wv = Wsf[(f_l + i) * 32 + c];
                    #pragma unroll
                    for (int j = 0; j < 8; j++) acc[i][j] += wv * xv[j];
                }
            }
            __syncthreads();
        }
        #pragma unroll
        for (int i = 0; i < 16; i++) {
            float b = bias[f_l + i];
            float* op = out + (size_t)(f_l + i) * 65536 + hw0f + hw_l;
            #pragma unroll
            for (int j = 0; j < 8; j++)
                op[j] = fmaxf(acc[i][j] + b, 0.0f);
        }
    } else {
        for (int it = 0; it < 32; it++) __syncthreads();
    }
#endif
}

extern "C" void kernel_launch(void* const* d_in, const int* in_sizes, int n_in,
                              void* d_out, int out_size) {
    const float* X = (const float*)d_in[0];      // [1,512,256,256]
    const float* W = (const float*)d_in[1];      // [512,512] (already masked)
    const float* bias = (const float*)d_in[n_in - 1];
    for (int i = 1; i < n_in; i++)
        if (in_sizes[i] == 512) { bias = (const float*)d_in[i]; break; }
    float* out = (float*)d_out;

    static bool attr_done = false;
    if (!attr_done) {
        cudaFuncSetAttribute(spconv_kernel,
                             cudaFuncAttributeMaxDynamicSharedMemorySize, SMEM_TOTAL);
        attr_done = true;
    }

    wprep_kernel<<<32, 256>>>(W);
    spconv_kernel<<<512, NTHREADS, SMEM_TOTAL>>>(X, W, bias, out);
}

// round 15
// speedup vs baseline: 1.0019x; 1.0019x over previous
#include <cuda_runtime.h>
#include <cuda_bf16.h>
#include <cstdint>

// ---------------- arch-feature gate ----------------
#if defined(__CUDA_ARCH_FEAT_SM103_ALL) || defined(__CUDA_ARCH_FEAT_SM100_ALL) || \
    defined(__CUDA_ARCH_FEAT_SM101_ALL) ||                                        \
    (defined(__CUDA_ARCH_SPECIFIC__) && (__CUDA_ARCH_SPECIFIC__ >= 1000))
#define HAS_TCGEN05 1
#else
#define HAS_TCGEN05 0
#endif

// ---------------- problem/tiling ----------------
// out[f, hw] = relu( sum_c W[f,c] * X[c,hw] + b[f] ),  F=C=512, HW=65536.
// 2-CTA cluster cg2 MMA: cluster tile D[hw=256 (128/CTA), f=512].
// R15: f split into 4 INDEPENDENT accumulator chains (N=128 dispatches,
// D at tmem+j*128), round-robin issue — hides the same-accumulator RMW
// turnaround that pinned tensor duty at ~46% in R6/R12/R13/R14.
// K=512 in 16 chunks of 32; 3 passes: Ah*Bh + Ah*Bl + Al*Bh (bf16 split).
#define NCHUNK 16
#define NSTAGE 3
#define NTHREADS 544          // 512 producers (warps 0-15) + MMA warp (16)
#define PRODS 512

// Prepacked W (1 MB): g_WP[ch][rank][j(4)][i(64)][128B row = hi c32 | lo c32],
// f = j*128 + rank*64 + i, pre-SW128-swizzled by i%8.
__device__ __align__(128) unsigned char g_WP[16ull * 512ull * 128ull];

// ---------------- smem layout ----------------
#define STAGE0   4096
#define STAGE_SZ 49152
#define A_OFF    0
#define B_OFF    16384
#define XS_OFF   (STAGE0 + NSTAGE * STAGE_SZ)     // 151552
#define BIAS_OFF 2048
#define SMEM_TOTAL (XS_OFF + 2 * 16384)           // 184320
#define MBAR_FULL(s)  (16u + 16u * (s))
#define MBAR_EMPTY(s) (64u + 16u * (s))
#define MBAR_PEER(s)  (112u + 16u * (s))
#define MBAR_DONE     160u

// idesc kind::f16 cg2: dtype=F32(b4), atype=BF16(b7), btype=BF16(b10),
// N=128 -> 16<<17, M_TOTAL=256 -> 16<<24
static constexpr unsigned IDESC =
    (1u << 4) | (1u << 7) | (1u << 10) | (16u << 17) | (16u << 24);

__device__ __forceinline__ uint32_t smem_u32(const void* p) {
    uint32_t a;
    asm("{ .reg .u64 t; cvta.to.shared.u64 t, %1; cvt.u32.u64 %0, t; }" : "=r"(a) : "l"(p));
    return a;
}
__device__ __forceinline__ uint32_t pack_lo_bf16x2(float x0, float x1) {
    __nv_bfloat162 p = __floats2bfloat162_rn(x0, x1);
    return *reinterpret_cast<uint32_t*>(&p);
}

#if HAS_TCGEN05
__device__ __forceinline__ uint32_t ctarank() {
    uint32_t r;
    asm("mov.u32 %0, %%cluster_ctarank;" : "=r"(r));
    return r;
}
__device__ __forceinline__ void cluster_sync() {
    asm volatile("barrier.cluster.arrive.aligned;" ::: "memory");
    asm volatile("barrier.cluster.wait.aligned;" ::: "memory");
}
__device__ __forceinline__ void mbar_init(uint32_t a, uint32_t cnt) {
    asm volatile("mbarrier.init.shared.b64 [%0], %1;" :: "r"(a), "r"(cnt) : "memory");
}
__device__ __forceinline__ void mbar_arrive(uint32_t a) {
    asm volatile("mbarrier.arrive.shared.b64 _, [%0];" :: "r"(a) : "memory");
}
__device__ __forceinline__ void mbar_arrive_rank0(uint32_t a) {
    asm volatile(
        "{\n\t.reg .b32 rem;\n\t"
        "mapa.shared::cluster.u32 rem, %0, 0;\n\t"
        "mbarrier.arrive.shared::cluster.b64 _, [rem];\n\t}"
        :: "r"(a) : "memory");
}
__device__ __forceinline__ void mbar_wait(uint32_t a, uint32_t parity) {
    asm volatile(
        "{\n\t.reg .pred P;\n\t"
        "WL%=:\n\t"
        "mbarrier.try_wait.parity.acquire.cta.shared::cta.b64 P, [%0], %1, 0x989680;\n\t"
        "@!P bra WL%=;\n\t}"
        :: "r"(a), "r"(parity) : "memory");
}
__device__ __forceinline__ void expect_tx(uint32_t a, uint32_t bytes) {
    asm volatile("mbarrier.arrive.expect_tx.shared.b64 _, [%0], %1;"
                 :: "r"(a), "r"(bytes) : "memory");
}
__device__ __forceinline__ void bulk_g2s(uint32_t dst, uint64_t gsrc,
                                         uint32_t bytes, uint32_t mbar) {
    asm volatile(
        "cp.async.bulk.shared::cluster.global.mbarrier::complete_tx::bytes "
        "[%0], [%1], %2, [%3];"
        :: "r"(dst), "l"(gsrc), "r"(bytes), "r"(mbar) : "memory");
}
__device__ __forceinline__ uint64_t sw128_desc_k(uint32_t addr) {
    return (2ull << 61) | (1ull << 46) | (64ull << 32) | (1ull << 16) |
           ((uint64_t)(addr >> 4) & 0x3FFFull);
}
__device__ __forceinline__ void mma_ss_cg2(uint32_t d, uint64_t ad, uint64_t bd,
                                           uint32_t en) {
    asm volatile(
        "{\n\t.reg .pred p;\n\tsetp.ne.u32 p, %5, 0;\n\t"
        "tcgen05.mma.cta_group::2.kind::f16 [%0], %1, %2, %3, "
        "{%4, %4, %4, %4, %4, %4, %4, %4}, p;\n\t}"
        :: "r"(d), "l"(ad), "l"(bd), "r"(IDESC), "r"(0u), "r"(en) : "memory");
}
__device__ __forceinline__ void mma_commit_mc2(uint32_t mbar) {
    asm volatile(
        "tcgen05.commit.cta_group::2.mbarrier::arrive::one.shared::cluster"
        ".multicast::cluster.b64 [%0], %1;"
        :: "r"(mbar), "h"((uint16_t)0x3) : "memory");
}
__device__ __forceinline__ void ldtm_x32(uint32_t* r, uint32_t a) {
    asm volatile(
        "tcgen05.ld.sync.aligned.32x32b.x32.b32 "
        "{%0, %1, %2, %3, %4, %5, %6, %7, "
        " %8, %9, %10, %11, %12, %13, %14, %15, "
        " %16, %17, %18, %19, %20, %21, %22, %23, "
        " %24, %25, %26, %27, %28, %29, %30, %31}, [%32];"
        : "=r"(r[0]),  "=r"(r[1]),  "=r"(r[2]),  "=r"(r[3]),
          "=r"(r[4]),  "=r"(r[5]),  "=r"(r[6]),  "=r"(r[7]),
          "=r"(r[8]),  "=r"(r[9]),  "=r"(r[10]), "=r"(r[11]),
          "=r"(r[12]), "=r"(r[13]), "=r"(r[14]), "=r"(r[15]),
          "=r"(r[16]), "=r"(r[17]), "=r"(r[18]), "=r"(r[19]),
          "=r"(r[20]), "=r"(r[21]), "=r"(r[22]), "=r"(r[23]),
          "=r"(r[24]), "=r"(r[25]), "=r"(r[26]), "=r"(r[27]),
          "=r"(r[28]), "=r"(r[29]), "=r"(r[30]), "=r"(r[31])
        : "r"(a));
}
#endif  // HAS_TCGEN05

// =====================================================================
// W prepass (~6us): g_WP[ch][rank][j][i][128B], f = j*128 + rank*64 + i.
// =====================================================================
__global__ void __launch_bounds__(256) wprep_kernel(const float* __restrict__ W) {
    int item = blockIdx.x * 256 + threadIdx.x;   // 8192 items
    int f = item >> 4;
    int ch = item & 15;
    int j    = f >> 7;           // chain 0..3
    int rank = (f >> 6) & 1;     // CTA rank providing this row
    int i    = f & 63;           // row within the 64-row slice
    const float* wr = W + (size_t)f * 512 + ch * 32;
    float v[32];
    #pragma unroll
    for (int q = 0; q < 8; q++)
        *reinterpret_cast<float4*>(v + 4 * q) =
            *reinterpret_cast<const float4*>(wr + 4 * q);
    uint32_t hi[16], lo[16];
    #pragma unroll
    for (int p = 0; p < 16; p++) {
        uint32_t u0 = __float_as_uint(v[2 * p]), u1 = __float_as_uint(v[2 * p + 1]);
        hi[p] = __byte_perm(u0, u1, 0x7632);
        lo[p] = pack_lo_bf16x2(v[2 * p]     - __uint_as_float(u0 & 0xFFFF0000u),
                               v[2 * p + 1] - __uint_as_float(u1 & 0xFFFF0000u));
    }
    unsigned char* row = g_WP +
        ((((size_t)ch * 2 + rank) * 4 + j) * 64 + i) * 128;
    int r7 = i & 7;
    #pragma unroll
    for (int q = 0; q < 4; q++)
        *reinterpret_cast<uint4*>(row + ((q ^ r7) * 16)) =
            make_uint4(hi[4 * q], hi[4 * q + 1], hi[4 * q + 2], hi[4 * q + 3]);
    #pragma unroll
    for (int q = 0; q < 4; q++)
        *reinterpret_cast<uint4*>(row + (((q + 4) ^ r7) * 16)) =
            make_uint4(lo[4 * q], lo[4 * q + 1], lo[4 * q + 2], lo[4 * q + 3]);
}

// =====================================================================
// Main GEMM. grid=512 (clusters of 2), 544 threads.
// =====================================================================
__global__ void __launch_bounds__(NTHREADS, 1) __cluster_dims__(2, 1, 1)
spconv_kernel(const float* __restrict__ X, const float* __restrict__ W,
              const float* __restrict__ bias, float* __restrict__ out)
{
    extern __shared__ char smem[];
    const int tid = threadIdx.x;

#if HAS_TCGEN05
    const uint32_t sb = smem_u32(smem);
    const int wid = tid >> 5;
    const int lane = tid & 31;
    const uint32_t rank = ctarank();
    const int hw0 = (blockIdx.x >> 1) * 256;
    const int hwA0 = hw0 + (int)rank * 128;      // this CTA's A rows

    if (wid == 0) {
        asm volatile("tcgen05.alloc.cta_group::2.sync.aligned.shared::cta.b32 [%0], %1;"
                     :: "r"(sb), "r"(512u) : "memory");
        asm volatile("tcgen05.relinquish_alloc_permit.cta_group::2.sync.aligned;" ::: "memory");
    }
    if (tid == 0) {
        #pragma unroll
        for (int s = 0; s < NSTAGE; s++) {
            mbar_init(sb + MBAR_FULL(s), PRODS + 1);     // producers + expect_tx
            mbar_init(sb + MBAR_EMPTY(s), 1);            // multicast commit
            mbar_init(sb + MBAR_PEER(s), 1);             // rank1 cluster-arrive
        }
        mbar_init(sb + MBAR_DONE, 1);
    }
    if (tid < PRODS)
        reinterpret_cast<float*>(smem + BIAS_OFF)[tid] = bias[tid];
    __syncthreads();
    cluster_sync();                               // barriers visible cluster-wide
    uint32_t tmem;
    asm volatile("ld.shared.b32 %0, [%1];" : "=r"(tmem) : "r"(sb));

    if (tid < PRODS) {
        // ================= producer warps 0-15 =================
        uint64_t wg;
        asm("cvta.to.global.u64 %0, %1;" : "=l"(wg) : "l"((const void*)g_WP));
        wg += (uint64_t)rank * 32768;             // [ch][rank][j][i]

        const int xc = tid >> 5;                  // 0..15
        const int xq = tid & 31;                  // 0..31
        const float* xbase = X + hwA0 + xq * 4;

        float4 pf0 = *reinterpret_cast<const float4*>(xbase + (size_t)xc * 65536);
        float4 pf1 = *reinterpret_cast<const float4*>(xbase + (size_t)(xc + 16) * 65536);

        int pst = 0, pph = 1;
        for (int ch = 0; ch < NCHUNK; ch++) {
            mbar_wait(sb + MBAR_EMPTY(pst), (uint32_t)pph);
            char* stg = smem + STAGE0 + pst * STAGE_SZ;
            const uint32_t stb = sb + STAGE0 + pst * STAGE_SZ;
            float* Xs = reinterpret_cast<float*>(smem + XS_OFF + (ch & 1) * 16384);

            if (tid == 0) {
                expect_tx(sb + MBAR_FULL(pst), 32768u);
                bulk_g2s(stb + B_OFF, wg + (uint64_t)ch * 65536ull, 32768u,
                         sb + MBAR_FULL(pst));
            }

            // drain prefetched fp32 X into staging [32 c][128 hw]
            *reinterpret_cast<float4*>(&Xs[xc * 128 + xq * 4]) = pf0;
            *reinterpret_cast<float4*>(&Xs[(xc + 16) * 128 + xq * 4]) = pf1;
            asm volatile("bar.sync 1, %0;" :: "r"(PRODS) : "memory");

            if (ch + 1 < NCHUNK) {
                pf0 = *reinterpret_cast<const float4*>(
                    xbase + (size_t)((ch + 1) * 32 + xc) * 65536);
                pf1 = *reinterpret_cast<const float4*>(
                    xbase + (size_t)((ch + 1) * 32 + xc + 16) * 65536);
            }

            // transpose + convert: thread owns (hw row, 8-c octet)
            {
                const int hwl = tid & 127;
                const int h   = tid >> 7;         // c in [8h, 8h+8)
                float v[8];
                #pragma unroll
                for (int q = 0; q < 8; q++)
                    v[q] = Xs[(h * 8 + q) * 128 + hwl];
                uint32_t hi[4], lo[4];
                #pragma unroll
                for (int p = 0; p < 4; p++) {
                    uint32_t u0 = __float_as_uint(v[2 * p]);
                    uint32_t u1 = __float_as_uint(v[2 * p + 1]);
                    hi[p] = __byte_perm(u0, u1, 0x7632);
                    lo[p] = pack_lo_bf16x2(
                        v[2 * p]     - __uint_as_float(u0 & 0xFFFF0000u),
                        v[2 * p + 1] - __uint_as_float(u1 & 0xFFFF0000u));
                }
                unsigned char* row = reinterpret_cast<unsigned char*>(stg + A_OFF) +
                                     (size_t)hwl * 128;
                const int r7 = hwl & 7;
                *reinterpret_cast<uint4*>(row + ((h ^ r7) * 16)) =
                    make_uint4(hi[0], hi[1], hi[2], hi[3]);
                *reinterpret_cast<uint4*>(row + (((4 + h) ^ r7) * 16)) =
                    make_uint4(lo[0], lo[1], lo[2], lo[3]);
            }

            mbar_arrive(sb + MBAR_FULL(pst));
            if (++pst == NSTAGE) { pst = 0; pph ^= 1; }
        }
    } else if (tid == PRODS) {
        // ================= dedicated MMA thread (warp 16, lane 0) ==========
        int cst = 0, cph = 0;
        for (int ch = 0; ch < NCHUNK; ch++) {
            const uint32_t stb = sb + STAGE0 + cst * STAGE_SZ;
            if (rank == 1) {
                mbar_wait(sb + MBAR_FULL(cst), (uint32_t)cph);
                asm volatile("fence.proxy.async.shared::cta;" ::: "memory");
                mbar_arrive_rank0(sb + MBAR_PEER(cst));
            } else {
                mbar_wait(sb + MBAR_FULL(cst), (uint32_t)cph);
                mbar_wait(sb + MBAR_PEER(cst), (uint32_t)cph);
                asm volatile("fence.proxy.async.shared::cta;" ::: "memory");
                uint64_t ad = sw128_desc_k(stb + A_OFF);
                // 24 dispatches: round-robin over 4 independent D chains.
                #pragma unroll
                for (int k = 0; k < 2; k++) {            // K=16 steps
                    uint64_t ah = ad + k * 2, al = ad + 4 + k * 2;
                    #pragma unroll
                    for (int pass = 0; pass < 3; pass++) {
                        uint64_t aop = (pass == 2) ? al : ah;
                        uint32_t en = (ch == 0 && k == 0 && pass == 0) ? 0u : 1u;
                        #pragma unroll
                        for (int j = 0; j < 4; j++) {    // chains (N=128)
                            uint64_t bdj = sw128_desc_k(stb + B_OFF + j * 8192);
                            uint64_t bop = (pass == 1) ? (bdj + 4 + k * 2)
                                                       : (bdj + k * 2);
                            mma_ss_cg2(tmem + j * 128, aop, bop, en);
                        }
                    }
                }
                mma_commit_mc2(sb + MBAR_EMPTY(cst));    // flips both CTAs
                if (ch == NCHUNK - 1) mma_commit_mc2(sb + MBAR_DONE);
            }
            if (++cst == NSTAGE) { cst = 0; cph ^= 1; }
        }
    }

    // ---- epilogue: producer warps read 128 hw rows x 512 f cols ----
    if (wid < 16) {
        mbar_wait(sb + MBAR_DONE, 0u);
        asm volatile("tcgen05.fence::after_thread_sync;" ::: "memory");

        const float* bias_s = reinterpret_cast<const float*>(smem + BIAS_OFF);
        const int sub = wid & 3;                 // TMEM subpartition
        const int cg  = wid >> 2;                // column group (0..3)
        const int hw  = hwA0 + sub * 32 + lane;
        #pragma unroll
        for (int cb = 0; cb < 4; cb++) {
            uint32_t col = (uint32_t)(cg * 128 + cb * 32);  // col == f (linear)
            uint32_t r[32];
            ldtm_x32(r, tmem + col);
            asm volatile("tcgen05.wait::ld.sync.aligned;" ::: "memory");
            float* op = out + (size_t)col * 65536 + hw;
            #pragma unroll
            for (int q = 0; q < 32; q++) {
                float v = __uint_as_float(r[q]) + bias_s[col + q];
                op[(size_t)q * 65536] = fmaxf(v, 0.0f);
            }
        }
    }

    __syncthreads();
    cluster_sync();                               // both CTAs done reading TMEM
    if (wid == 0) {
        asm volatile("tcgen05.dealloc.cta_group::2.sync.aligned.b32 %0, %1;"
                     :: "r"(tmem), "r"(512u));
    }
    cluster_sync();

#else
    // ========= FFMA fallback (plain pass; never executes on GB300) =========
    if (tid < 512) {
        float* Xsf = reinterpret_cast<float*>(smem);            // [32][128]
        float* Wsf = reinterpret_cast<float*>(smem + 16384);    // [512][32]
        const int hw0f = (int)blockIdx.x * 128;
        const int tx = tid & 15, ty = tid >> 4;
        const int hw_l = tx * 8, f_l = ty * 16;
        float acc[16][8];
        #pragma unroll
        for (int i = 0; i < 16; i++)
            #pragma unroll
            for (int j = 0; j < 8; j++) acc[i][j] = 0.0f;
        for (int ch = 0; ch < 16; ch++) {
            const int c0 = ch * 32;
            #pragma unroll
            for (int i = 0; i < 2; i++) {
                int l = tid + 512 * i, row = l >> 5, c4 = l & 31;
                *reinterpret_cast<float4*>(&Xsf[row * 128 + c4 * 4]) =
                    *reinterpret_cast<const float4*>(
                        &X[(size_t)(c0 + row) * 65536 + hw0f + c4 * 4]);
            }
            #pragma unroll
            for (int i = 0; i < 8; i++) {
                int l = tid + 512 * i, row = l >> 3, c4 = l & 7;
                *reinterpret_cast<float4*>(&Wsf[row * 32 + c4 * 4]) =
                    *reinterpret_cast<const float4*>(
                        &W[(size_t)row * 512 + c0 + c4 * 4]);
            }
            __syncthreads();
            #pragma unroll 4
            for (int c = 0; c < 32; c++) {
                float xv[8];
                *reinterpret_cast<float4*>(xv) =
                    *reinterpret_cast<float4*>(&Xsf[c * 128 + hw_l]);
                *reinterpret_cast<float4*>(xv + 4) =
                    *reinterpret_cast<float4*>(&Xsf[c * 128 + hw_l + 4]);
                #pragma unroll
                for (int i = 0; i < 16; i++) {
                    float wv = Wsf[(f_l + i) * 32 + c];
                    #pragma unroll
                    for (int j = 0; j < 8; j++) acc[i][j] += wv * xv[j];
                }
            }
            __syncthreads();
        }
        #pragma unroll
        for (int i = 0; i < 16; i++) {
            float b = bias[f_l + i];
            float* op = out + (size_t)(f_l + i) * 65536 + hw0f + hw_l;
            #pragma unroll
            for (int j = 0; j < 8; j++)
                op[j] = fmaxf(acc[i][j] + b, 0.0f);
        }
    } else {
        for (int it = 0; it < 32; it++) __syncthreads();
    }
#endif
}

extern "C" void kernel_launch(void* const* d_in, const int* in_sizes, int n_in,
                              void* d_out, int out_size) {
    const float* X = (const float*)d_in[0];      // [1,512,256,256]
    const float* W = (const float*)d_in[1];      // [512,512] (already masked)
    const float* bias = (const float*)d_in[n_in - 1];
    for (int i = 1; i < n_in; i++)
        if (in_sizes[i] == 512) { bias = (const float*)d_in[i]; break; }
    float* out = (float*)d_out;

    static bool attr_done = false;
    if (!attr_done) {
        cudaFuncSetAttribute(spconv_kernel,
                             cudaFuncAttributeMaxDynamicSharedMemorySize, SMEM_TOTAL);
        attr_done = true;
    }

    wprep_kernel<<<32, 256>>>(W);
    spconv_kernel<<<512, NTHREADS, SMEM_TOTAL>>>(X, W, bias, out);
}

// round 16
// speedup vs baseline: 1.0900x; 1.0880x over previous
#include <cuda_runtime.h>
#include <cuda_fp16.h>
#include <cstdint>

// ---------------- arch-feature gate ----------------
#if defined(__CUDA_ARCH_FEAT_SM103_ALL) || defined(__CUDA_ARCH_FEAT_SM100_ALL) || \
    defined(__CUDA_ARCH_FEAT_SM101_ALL) ||                                        \
    (defined(__CUDA_ARCH_SPECIFIC__) && (__CUDA_ARCH_SPECIFIC__ >= 1000))
#define HAS_TCGEN05 1
#else
#define HAS_TCGEN05 0
#endif

// ---------------- problem/tiling ----------------
// out[f, hw] = relu( sum_c W[f,c] * X[c,hw] + b[f] ),  F=C=512, HW=65536.
// 2-CTA cluster cg2 MMA: cluster tile D[hw=256 (128/CTA), f=512 (2 disp N=256,
// B split per CTA)]. A = X^T K-major, converted once chip-wide.
// R16: 2-PASS FP16 numerics — X split exactly into Xh+Xl (fp16), W quantized
// once to fp16 RN:  X*W = Xh*W + Xl*W.  33% less tensor work than the 3-pass
// bf16 split (SS-mode runs at ~half rate, so work is the binding resource).
// K=512 in 8 superchunks of 64 (4 k-steps each).
#define NSC 8
#define NSTAGE 2
#define NTHREADS 544          // 512 producers (warps 0-15) + MMA warp (16)
#define PRODS 512

// Prepacked W (512 KB): g_WP[sc][rank][disp][fr][128B row = 64 c fp16],
// f = disp*256 + rank*128 + fr, pre-SW128-swizzled by fr%8.
__device__ __align__(128) unsigned char g_WP[8ull * 512ull * 128ull];

// ---------------- smem layout ----------------
// 0: tmem ptr | 16+16s: FULL[s] | 64+16s: EMPTY[s] | 112+16s: PEER[s] | 160: DONE
// 2048: bias (512 f) | 4096 + s*65536: stage s {A_HI 16K | A_LO 16K | B 32K}
// 135168 + b*32768: Xs fp32 staging [64 c][128 hw], b = sc&1
#define STAGE0   4096
#define STAGE_SZ 65536
#define A_HI     0
#define A_LO     16384
#define B_OFF    32768
#define XS_OFF   (STAGE0 + NSTAGE * STAGE_SZ)     // 135168
#define BIAS_OFF 2048
#define SMEM_TOTAL (XS_OFF + 2 * 32768)           // 200704
#define MBAR_FULL(s)  (16u + 16u * (s))
#define MBAR_EMPTY(s) (64u + 16u * (s))
#define MBAR_PEER(s)  (112u + 16u * (s))
#define MBAR_DONE     160u

// idesc kind::f16 cg2: dtype=F32(b4), atype=F16(0), btype=F16(0),
// N=256 -> 32<<17, M_TOTAL=256 -> 16<<24
static constexpr unsigned IDESC = (1u << 4) | (32u << 17) | (16u << 24);

__device__ __forceinline__ uint32_t smem_u32(const void* p) {
    uint32_t a;
    asm("{ .reg .u64 t; cvta.to.shared.u64 t, %1; cvt.u32.u64 %0, t; }" : "=r"(a) : "l"(p));
    return a;
}
__device__ __forceinline__ uint32_t pack_h2(float x0, float x1) {
    __half2 p = __floats2half2_rn(x0, x1);
    return *reinterpret_cast<uint32_t*>(&p);
}

#if HAS_TCGEN05
__device__ __forceinline__ uint32_t ctarank() {
    uint32_t r;
    asm("mov.u32 %0, %%cluster_ctarank;" : "=r"(r));
    return r;
}
__device__ __forceinline__ void cluster_sync() {
    asm volatile("barrier.cluster.arrive.aligned;" ::: "memory");
    asm volatile("barrier.cluster.wait.aligned;" ::: "memory");
}
__device__ __forceinline__ void mbar_init(uint32_t a, uint32_t cnt) {
    asm volatile("mbarrier.init.shared.b64 [%0], %1;" :: "r"(a), "r"(cnt) : "memory");
}
__device__ __forceinline__ void mbar_arrive(uint32_t a) {
    asm volatile("mbarrier.arrive.shared.b64 _, [%0];" :: "r"(a) : "memory");
}
__device__ __forceinline__ void mbar_arrive_rank0(uint32_t a) {
    asm volatile(
        "{\n\t.reg .b32 rem;\n\t"
        "mapa.shared::cluster.u32 rem, %0, 0;\n\t"
        "mbarrier.arrive.shared::cluster.b64 _, [rem];\n\t}"
        :: "r"(a) : "memory");
}
__device__ __forceinline__ void mbar_wait(uint32_t a, uint32_t parity) {
    asm volatile(
        "{\n\t.reg .pred P;\n\t"
        "WL%=:\n\t"
        "mbarrier.try_wait.parity.acquire.cta.shared::cta.b64 P, [%0], %1, 0x989680;\n\t"
        "@!P bra WL%=;\n\t}"
        :: "r"(a), "r"(parity) : "memory");
}
__device__ __forceinline__ void expect_tx(uint32_t a, uint32_t bytes) {
    asm volatile("mbarrier.arrive.expect_tx.shared.b64 _, [%0], %1;"
                 :: "r"(a), "r"(bytes) : "memory");
}
__device__ __forceinline__ void bulk_g2s(uint32_t dst, uint64_t gsrc,
                                         uint32_t bytes, uint32_t mbar) {
    asm volatile(
        "cp.async.bulk.shared::cluster.global.mbarrier::complete_tx::bytes "
        "[%0], [%1], %2, [%3];"
        :: "r"(dst), "l"(gsrc), "r"(bytes), "r"(mbar) : "memory");
}
__device__ __forceinline__ uint64_t sw128_desc_k(uint32_t addr) {
    return (2ull << 61) | (1ull << 46) | (64ull << 32) | (1ull << 16) |
           ((uint64_t)(addr >> 4) & 0x3FFFull);
}
__device__ __forceinline__ void mma_ss_cg2(uint32_t d, uint64_t ad, uint64_t bd,
                                           uint32_t en) {
    asm volatile(
        "{\n\t.reg .pred p;\n\tsetp.ne.u32 p, %5, 0;\n\t"
        "tcgen05.mma.cta_group::2.kind::f16 [%0], %1, %2, %3, "
        "{%4, %4, %4, %4, %4, %4, %4, %4}, p;\n\t}"
        :: "r"(d), "l"(ad), "l"(bd), "r"(IDESC), "r"(0u), "r"(en) : "memory");
}
__device__ __forceinline__ void mma_commit_mc2(uint32_t mbar) {
    asm volatile(
        "tcgen05.commit.cta_group::2.mbarrier::arrive::one.shared::cluster"
        ".multicast::cluster.b64 [%0], %1;"
        :: "r"(mbar), "h"((uint16_t)0x3) : "memory");
}
__device__ __forceinline__ void ldtm_x32(uint32_t* r, uint32_t a) {
    asm volatile(
        "tcgen05.ld.sync.aligned.32x32b.x32.b32 "
        "{%0, %1, %2, %3, %4, %5, %6, %7, "
        " %8, %9, %10, %11, %12, %13, %14, %15, "
        " %16, %17, %18, %19, %20, %21, %22, %23, "
        " %24, %25, %26, %27, %28, %29, %30, %31}, [%32];"
        : "=r"(r[0]),  "=r"(r[1]),  "=r"(r[2]),  "=r"(r[3]),
          "=r"(r[4]),  "=r"(r[5]),  "=r"(r[6]),  "=r"(r[7]),
          "=r"(r[8]),  "=r"(r[9]),  "=r"(r[10]), "=r"(r[11]),
          "=r"(r[12]), "=r"(r[13]), "=r"(r[14]), "=r"(r[15]),
          "=r"(r[16]), "=r"(r[17]), "=r"(r[18]), "=r"(r[19]),
          "=r"(r[20]), "=r"(r[21]), "=r"(r[22]), "=r"(r[23]),
          "=r"(r[24]), "=r"(r[25]), "=r"(r[26]), "=r"(r[27]),
          "=r"(r[28]), "=r"(r[29]), "=r"(r[30]), "=r"(r[31])
        : "r"(a));
}
#endif  // HAS_TCGEN05

// =====================================================================
// W prepass (~4us): g_WP[sc][rank][disp][fr][128B = 64 c fp16],
// f = disp*256 + rank*128 + fr. 4096 items (f, sc).
// =====================================================================
__global__ void __launch_bounds__(256) wprep_kernel(const float* __restrict__ W) {
    int item = blockIdx.x * 256 + threadIdx.x;   // 4096 items
    int f  = item >> 3;
    int sc = item & 7;
    int disp = f >> 8;
    int rank = (f >> 7) & 1;
    int fr = f & 127;
    const float* wr = W + (size_t)f * 512 + sc * 64;
    float v[64];
    #pragma unroll
    for (int q = 0; q < 16; q++)
        *reinterpret_cast<float4*>(v + 4 * q) =
            *reinterpret_cast<const float4*>(wr + 4 * q);
    uint32_t h[32];
    #pragma unroll
    for (int p = 0; p < 32; p++)
        h[p] = pack_h2(v[2 * p], v[2 * p + 1]);
    unsigned char* row = g_WP +
        ((((size_t)sc * 2 + rank) * 2 + disp) * 128 + fr) * 128;
    int r7 = fr & 7;
    #pragma unroll
    for (int u = 0; u < 8; u++)
        *reinterpret_cast<uint4*>(row + ((u ^ r7) * 16)) =
            make_uint4(h[4 * u], h[4 * u + 1], h[4 * u + 2], h[4 * u + 3]);
}

// =====================================================================
// Main GEMM. grid=512 (clusters of 2), 544 threads.
// =====================================================================
__global__ void __launch_bounds__(NTHREADS, 1) __cluster_dims__(2, 1, 1)
spconv_kernel(const float* __restrict__ X, const float* __restrict__ W,
              const float* __restrict__ bias, float* __restrict__ out)
{
    extern __shared__ char smem[];
    const int tid = threadIdx.x;

#if HAS_TCGEN05
    const uint32_t sb = smem_u32(smem);
    const int wid = tid >> 5;
    const int lane = tid & 31;
    const uint32_t rank = ctarank();
    const int hw0 = (blockIdx.x >> 1) * 256;
    const int hwA0 = hw0 + (int)rank * 128;      // this CTA's A rows

    if (wid == 0) {
        asm volatile("tcgen05.alloc.cta_group::2.sync.aligned.shared::cta.b32 [%0], %1;"
                     :: "r"(sb), "r"(512u) : "memory");
        asm volatile("tcgen05.relinquish_alloc_permit.cta_group::2.sync.aligned;" ::: "memory");
    }
    if (tid == 0) {
        #pragma unroll
        for (int s = 0; s < NSTAGE; s++) {
            mbar_init(sb + MBAR_FULL(s), PRODS + 1);     // producers + expect_tx
            mbar_init(sb + MBAR_EMPTY(s), 1);            // multicast commit
            mbar_init(sb + MBAR_PEER(s), 1);             // rank1 cluster-arrive
        }
        mbar_init(sb + MBAR_DONE, 1);
    }
    if (tid < PRODS)
        reinterpret_cast<float*>(smem + BIAS_OFF)[tid] = bias[tid];
    __syncthreads();
    cluster_sync();                               // barriers visible cluster-wide
    uint32_t tmem;
    asm volatile("ld.shared.b32 %0, [%1];" : "=r"(tmem) : "r"(sb));

    if (tid < PRODS) {
        // ================= producer warps 0-15 =================
        uint64_t wg;
        asm("cvta.to.global.u64 %0, %1;" : "=l"(wg) : "l"((const void*)g_WP));
        wg += (uint64_t)rank * 32768;             // [sc][rank][disp][fr]

        const int xc = tid >> 5;                  // 0..15
        const int xq = tid & 31;                  // 0..31
        const float* xbase = X + hwA0 + xq * 4;

        float4 pf[4];
        #pragma unroll
        for (int i = 0; i < 4; i++)
            pf[i] = *reinterpret_cast<const float4*>(
                xbase + (size_t)(xc + 16 * i) * 65536);

        int pst = 0, pph = 1;
        for (int sc = 0; sc < NSC; sc++) {
            mbar_wait(sb + MBAR_EMPTY(pst), (uint32_t)pph);
            char* stg = smem + STAGE0 + pst * STAGE_SZ;
            const uint32_t stb = sb + STAGE0 + pst * STAGE_SZ;
            float* Xs = reinterpret_cast<float*>(smem + XS_OFF + (sc & 1) * 32768);

            if (tid == 0) {
                expect_tx(sb + MBAR_FULL(pst), 32768u);
                bulk_g2s(stb + B_OFF, wg + (uint64_t)sc * 65536ull, 32768u,
                         sb + MBAR_FULL(pst));
            }

            // drain prefetched fp32 X into staging [64 c][128 hw]
            #pragma unroll
            for (int i = 0; i < 4; i++)
                *reinterpret_cast<float4*>(&Xs[(xc + 16 * i) * 128 + xq * 4]) = pf[i];
            asm volatile("bar.sync 1, %0;" :: "r"(PRODS) : "memory");

            if (sc + 1 < NSC) {
                #pragma unroll
                for (int i = 0; i < 4; i++)
                    pf[i] = *reinterpret_cast<const float4*>(
                        xbase + (size_t)((sc + 1) * 64 + xc + 16 * i) * 65536);
            }

            // transpose + convert: thread owns (hw row, 16-c block)
            // X = Xh + Xl exact fp16 split
            {
                const int hwl = tid & 127;
                const int h   = tid >> 7;         // c block: [16h, 16h+16)
                float v[16];
                #pragma unroll
                for (int q = 0; q < 16; q++)
                    v[q] = Xs[(h * 16 + q) * 128 + hwl];   // conflict-free
                uint32_t hi[8], lo[8];
                #pragma unroll
                for (int p = 0; p < 8; p++) {
                    float a0 = v[2 * p], a1 = v[2 * p + 1];
                    __half h0 = __float2half_rn(a0);
                    __half h1 = __float2half_rn(a1);
                    __half2 hp = __halves2half2(h0, h1);
                    hi[p] = *reinterpret_cast<uint32_t*>(&hp);
                    lo[p] = pack_h2(a0 - __half2float(h0),
                                    a1 - __half2float(h1));
                }
                unsigned char* rh = reinterpret_cast<unsigned char*>(stg + A_HI) +
                                    (size_t)hwl * 128;
                unsigned char* rl = reinterpret_cast<unsigned char*>(stg + A_LO) +
                                    (size_t)hwl * 128;
                const int r7 = hwl & 7;
                #pragma unroll
                for (int u = 0; u < 2; u++) {
                    *reinterpret_cast<uint4*>(rh + (((2 * h + u) ^ r7) * 16)) =
                        make_uint4(hi[4 * u], hi[4 * u + 1], hi[4 * u + 2], hi[4 * u + 3]);
                    *reinterpret_cast<uint4*>(rl + (((2 * h + u) ^ r7) * 16)) =
                        make_uint4(lo[4 * u], lo[4 * u + 1], lo[4 * u + 2], lo[4 * u + 3]);
                }
            }

            mbar_arrive(sb + MBAR_FULL(pst));
            if (++pst == NSTAGE) { pst = 0; pph ^= 1; }
        }
    } else if (tid == PRODS) {
        // ================= dedicated MMA thread (warp 16, lane 0) ==========
        int cst = 0, cph = 0;
        for (int sc = 0; sc < NSC; sc++) {
            const uint32_t stb = sb + STAGE0 + cst * STAGE_SZ;
            if (rank == 1) {
                mbar_wait(sb + MBAR_FULL(cst), (uint32_t)cph);
                asm volatile("fence.proxy.async.shared::cta;" ::: "memory");
                mbar_arrive_rank0(sb + MBAR_PEER(cst));
            } else {
                mbar_wait(sb + MBAR_FULL(cst), (uint32_t)cph);
                mbar_wait(sb + MBAR_PEER(cst), (uint32_t)cph);
                asm volatile("fence.proxy.async.shared::cta;" ::: "memory");
                uint64_t adh = sw128_desc_k(stb + A_HI);
                uint64_t adl = sw128_desc_k(stb + A_LO);
                // 16 dispatches: 4 k-steps x 2 f-halves x (hi, lo)
                #pragma unroll
                for (int k = 0; k < 4; k++) {
                    #pragma unroll
                    for (int disp = 0; disp < 2; disp++) {
                        uint64_t bd = sw128_desc_k(stb + B_OFF + disp * 16384) + k * 2;
                        uint32_t d = tmem + disp * 256;
                        mma_ss_cg2(d, adh + k * 2, bd,
                                   (sc == 0 && k == 0) ? 0u : 1u);
                        mma_ss_cg2(d, adl + k * 2, bd, 1u);
                    }
                }
                mma_commit_mc2(sb + MBAR_EMPTY(cst));    // flips both CTAs
                if (sc == NSC - 1) mma_commit_mc2(sb + MBAR_DONE);
            }
            if (++cst == NSTAGE) { cst = 0; cph ^= 1; }
        }
    }

    // ---- epilogue: producer warps read 128 hw rows x 512 f cols ----
    if (wid < 16) {
        mbar_wait(sb + MBAR_DONE, 0u);
        asm volatile("tcgen05.fence::after_thread_sync;" ::: "memory");

        const float* bias_s = reinterpret_cast<const float*>(smem + BIAS_OFF);
        const int sub = wid & 3;                 // TMEM subpartition
        const int cg  = wid >> 2;                // column group (0..3)
        const int hw  = hwA0 + sub * 32 + lane;
        #pragma unroll
        for (int cb = 0; cb < 4; cb++) {
            uint32_t col = (uint32_t)(cg * 128 + cb * 32);  // col == f (linear)
            uint32_t r[32];
            ldtm_x32(r, tmem + col);
            asm volatile("tcgen05.wait::ld.sync.aligned;" ::: "memory");
            float* op = out + (size_t)col * 65536 + hw;
            #pragma unroll
            for (int q = 0; q < 32; q++) {
                float v = __uint_as_float(r[q]) + bias_s[col + q];
                op[(size_t)q * 65536] = fmaxf(v, 0.0f);
            }
        }
    }

    __syncthreads();
    cluster_sync();                               // both CTAs done reading TMEM
    if (wid == 0) {
        asm volatile("tcgen05.dealloc.cta_group::2.sync.aligned.b32 %0, %1;"
                     :: "r"(tmem), "r"(512u));
    }
    cluster_sync();

#else
    // ========= FFMA fallback (plain pass; never executes on GB300) =========
    if (tid < 512) {
        float* Xsf = reinterpret_cast<float*>(smem);            // [32][128]
        float* Wsf = reinterpret_cast<float*>(smem + 16384);    // [512][32]
        const int hw0f = (int)blockIdx.x * 128;
        const int tx = tid & 15, ty = tid >> 4;
        const int hw_l = tx * 8, f_l = ty * 16;
        float acc[16][8];
        #pragma unroll
        for (int i = 0; i < 16; i++)
            #pragma unroll
            for (int j = 0; j < 8; j++) acc[i][j] = 0.0f;
        for (int ch = 0; ch < 16; ch++) {
            const int c0 = ch * 32;
            #pragma unroll
            for (int i = 0; i < 2; i++) {
                int l = tid + 512 * i, row = l >> 5, c4 = l & 31;
                *reinterpret_cast<float4*>(&Xsf[row * 128 + c4 * 4]) =
                    *reinterpret_cast<const float4*>(
                        &X[(size_t)(c0 + row) * 65536 + hw0f + c4 * 4]);
            }
            #pragma unroll
            for (int i = 0; i < 8; i++) {
                int l = tid + 512 * i, row = l >> 3, c4 = l & 7;
                *reinterpret_cast<float4*>(&Wsf[row * 32 + c4 * 4]) =
                    *reinterpret_cast<const float4*>(
                        &W[(size_t)row * 512 + c0 + c4 * 4]);
            }
            __syncthreads();
            #pragma unroll 4
            for (int c = 0; c < 32; c++) {
                float xv[8];
                *reinterpret_cast<float4*>(xv) =
                    *reinterpret_cast<float4*>(&Xsf[c * 128 + hw_l]);
                *reinterpret_cast<float4*>(xv + 4) =
                    *reinterpret_cast<float4*>(&Xsf[c * 128 + hw_l + 4]);
                #pragma unroll
                for (int i = 0; i < 16; i++) {
                    float wv = Wsf[(f_l + i) * 32 + c];
                    #pragma unroll
                    for (int j = 0; j < 8; j++) acc[i][j] += wv * xv[j];
                }
            }
            __syncthreads();
        }
        #pragma unroll
        for (int i = 0; i < 16; i++) {
            float b = bias[f_l + i];
            float* op = out + (size_t)(f_l + i) * 65536 + hw0f + hw_l;
            #pragma unroll
            for (int j = 0; j < 8; j++)
                op[j] = fmaxf(acc[i][j] + b, 0.0f);
        }
    } else {
        for (int it = 0; it < 32; it++) __syncthreads();
    }
#endif
}

extern "C" void kernel_launch(void* const* d_in, const int* in_sizes, int n_in,
                              void* d_out, int out_size) {
    const float* X = (const float*)d_in[0];      // [1,512,256,256]
    const float* W = (const float*)d_in[1];      // [512,512] (already masked)
    const float* bias = (const float*)d_in[n_in - 1];
    for (int i = 1; i < n_in; i++)
        if (in_sizes[i] == 512) { bias = (const float*)d_in[i]; break; }
    float* out = (float*)d_out;

    static bool attr_done = false;
    if (!attr_done) {
        cudaFuncSetAttribute(spconv_kernel,
                             cudaFuncAttributeMaxDynamicSharedMemorySize, SMEM_TOTAL);
        attr_done = true;
    }

    wprep_kernel<<<16, 256>>>(W);
    spconv_kernel<<<512, NTHREADS, SMEM_TOTAL>>>(X, W, bias, out);
}

// round 17
// speedup vs baseline: 1.1176x; 1.0253x over previous
#include <cuda_runtime.h>
#include <cuda_fp16.h>
#include <cstdint>

// ---------------- arch-feature gate ----------------
#if defined(__CUDA_ARCH_FEAT_SM103_ALL) || defined(__CUDA_ARCH_FEAT_SM100_ALL) || \
    defined(__CUDA_ARCH_FEAT_SM101_ALL) ||                                        \
    (defined(__CUDA_ARCH_SPECIFIC__) && (__CUDA_ARCH_SPECIFIC__ >= 1000))
#define HAS_TCGEN05 1
#else
#define HAS_TCGEN05 0
#endif

// ---------------- problem/tiling ----------------
// out[f, hw] = relu( sum_c W[f,c] * X[c,hw] + b[f] ),  F=C=512, HW=65536.
// 2-CTA cluster cg2 MMA: cluster tile D[hw=256 (128/CTA), f=512 (2 disp N=256,
// B split per CTA)]. A = X^T K-major, converted once chip-wide.
// R17: SINGLE-PASS FP16 — X fp16 RN, W fp16 RN. Halves tensor work vs R16's
// 2-pass (SS-mode runs ~half rate, so elapsed scales with dispatch count).
// Error budget calibrated on R16: 2.06e-4 (W-only) -> sqrt(2)x ~ 2.9e-4.
// K=512 in 8 superchunks of 64 (4 k-steps x 2 f-halves = 8 dispatches each).
#define NSC 8
#define NSTAGE 3
#define NTHREADS 544          // 512 producers (warps 0-15) + MMA warp (16)
#define PRODS 512

// Prepacked W (512 KB): g_WP[sc][rank][disp][fr][128B row = 64 c fp16],
// f = disp*256 + rank*128 + fr, pre-SW128-swizzled by fr%8.
__device__ __align__(128) unsigned char g_WP[8ull * 512ull * 128ull];

// ---------------- smem layout ----------------
// 0: tmem ptr | 16+16s: FULL[s] | 64+16s: EMPTY[s] | 112+16s: PEER[s] | 160: DONE
// 2048: bias (512 f) | 4096 + s*49152: stage s {A 16K | B 32K}
// 151552 + b*32768: Xs fp32 staging [64 c][128 hw], b = sc&1
#define STAGE0   4096
#define STAGE_SZ 49152
#define A_OFF    0
#define B_OFF    16384
#define XS_OFF   (STAGE0 + NSTAGE * STAGE_SZ)     // 151552
#define BIAS_OFF 2048
#define SMEM_TOTAL (XS_OFF + 2 * 32768)           // 217088
#define MBAR_FULL(s)  (16u + 16u * (s))
#define MBAR_EMPTY(s) (64u + 16u * (s))
#define MBAR_PEER(s)  (112u + 16u * (s))
#define MBAR_DONE     160u

// idesc kind::f16 cg2: dtype=F32(b4), atype=F16(0), btype=F16(0),
// N=256 -> 32<<17, M_TOTAL=256 -> 16<<24
static constexpr unsigned IDESC = (1u << 4) | (32u << 17) | (16u << 24);

__device__ __forceinline__ uint32_t smem_u32(const void* p) {
    uint32_t a;
    asm("{ .reg .u64 t; cvta.to.shared.u64 t, %1; cvt.u32.u64 %0, t; }" : "=r"(a) : "l"(p));
    return a;
}
__device__ __forceinline__ uint32_t pack_h2(float x0, float x1) {
    __half2 p = __floats2half2_rn(x0, x1);
    return *reinterpret_cast<uint32_t*>(&p);
}

#if HAS_TCGEN05
__device__ __forceinline__ uint32_t ctarank() {
    uint32_t r;
    asm("mov.u32 %0, %%cluster_ctarank;" : "=r"(r));
    return r;
}
__device__ __forceinline__ void cluster_sync() {
    asm volatile("barrier.cluster.arrive.aligned;" ::: "memory");
    asm volatile("barrier.cluster.wait.aligned;" ::: "memory");
}
__device__ __forceinline__ void mbar_init(uint32_t a, uint32_t cnt) {
    asm volatile("mbarrier.init.shared.b64 [%0], %1;" :: "r"(a), "r"(cnt) : "memory");
}
__device__ __forceinline__ void mbar_arrive(uint32_t a) {
    asm volatile("mbarrier.arrive.shared.b64 _, [%0];" :: "r"(a) : "memory");
}
__device__ __forceinline__ void mbar_arrive_rank0(uint32_t a) {
    asm volatile(
        "{\n\t.reg .b32 rem;\n\t"
        "mapa.shared::cluster.u32 rem, %0, 0;\n\t"
        "mbarrier.arrive.shared::cluster.b64 _, [rem];\n\t}"
        :: "r"(a) : "memory");
}
__device__ __forceinline__ void mbar_wait(uint32_t a, uint32_t parity) {
    asm volatile(
        "{\n\t.reg .pred P;\n\t"
        "WL%=:\n\t"
        "mbarrier.try_wait.parity.acquire.cta.shared::cta.b64 P, [%0], %1, 0x989680;\n\t"
        "@!P bra WL%=;\n\t}"
        :: "r"(a), "r"(parity) : "memory");
}
__device__ __forceinline__ void expect_tx(uint32_t a, uint32_t bytes) {
    asm volatile("mbarrier.arrive.expect_tx.shared.b64 _, [%0], %1;"
                 :: "r"(a), "r"(bytes) : "memory");
}
__device__ __forceinline__ void bulk_g2s(uint32_t dst, uint64_t gsrc,
                                         uint32_t bytes, uint32_t mbar) {
    asm volatile(
        "cp.async.bulk.shared::cluster.global.mbarrier::complete_tx::bytes "
        "[%0], [%1], %2, [%3];"
        :: "r"(dst), "l"(gsrc), "r"(bytes), "r"(mbar) : "memory");
}
__device__ __forceinline__ uint64_t sw128_desc_k(uint32_t addr) {
    return (2ull << 61) | (1ull << 46) | (64ull << 32) | (1ull << 16) |
           ((uint64_t)(addr >> 4) & 0x3FFFull);
}
__device__ __forceinline__ void mma_ss_cg2(uint32_t d, uint64_t ad, uint64_t bd,
                                           uint32_t en) {
    asm volatile(
        "{\n\t.reg .pred p;\n\tsetp.ne.u32 p, %5, 0;\n\t"
        "tcgen05.mma.cta_group::2.kind::f16 [%0], %1, %2, %3, "
        "{%4, %4, %4, %4, %4, %4, %4, %4}, p;\n\t}"
        :: "r"(d), "l"(ad), "l"(bd), "r"(IDESC), "r"(0u), "r"(en) : "memory");
}
__device__ __forceinline__ void mma_commit_mc2(uint32_t mbar) {
    asm volatile(
        "tcgen05.commit.cta_group::2.mbarrier::arrive::one.shared::cluster"
        ".multicast::cluster.b64 [%0], %1;"
        :: "r"(mbar), "h"((uint16_t)0x3) : "memory");
}
__device__ __forceinline__ void ldtm_x32(uint32_t* r, uint32_t a) {
    asm volatile(
        "tcgen05.ld.sync.aligned.32x32b.x32.b32 "
        "{%0, %1, %2, %3, %4, %5, %6, %7, "
        " %8, %9, %10, %11, %12, %13, %14, %15, "
        " %16, %17, %18, %19, %20, %21, %22, %23, "
        " %24, %25, %26, %27, %28, %29, %30, %31}, [%32];"
        : "=r"(r[0]),  "=r"(r[1]),  "=r"(r[2]),  "=r"(r[3]),
          "=r"(r[4]),  "=r"(r[5]),  "=r"(r[6]),  "=r"(r[7]),
          "=r"(r[8]),  "=r"(r[9]),  "=r"(r[10]), "=r"(r[11]),
          "=r"(r[12]), "=r"(r[13]), "=r"(r[14]), "=r"(r[15]),
          "=r"(r[16]), "=r"(r[17]), "=r"(r[18]), "=r"(r[19]),
          "=r"(r[20]), "=r"(r[21]), "=r"(r[22]), "=r"(r[23]),
          "=r"(r[24]), "=r"(r[25]), "=r"(r[26]), "=r"(r[27]),
          "=r"(r[28]), "=r"(r[29]), "=r"(r[30]), "=r"(r[31])
        : "r"(a));
}
#endif  // HAS_TCGEN05

// =====================================================================
// W prepass (~4us): g_WP[sc][rank][disp][fr][128B = 64 c fp16].
// =====================================================================
__global__ void __launch_bounds__(256) wprep_kernel(const float* __restrict__ W) {
    int item = blockIdx.x * 256 + threadIdx.x;   // 4096 items
    int f  = item >> 3;
    int sc = item & 7;
    int disp = f >> 8;
    int rank = (f >> 7) & 1;
    int fr = f & 127;
    const float* wr = W + (size_t)f * 512 + sc * 64;
    float v[64];
    #pragma unroll
    for (int q = 0; q < 16; q++)
        *reinterpret_cast<float4*>(v + 4 * q) =
            *reinterpret_cast<const float4*>(wr + 4 * q);
    uint32_t h[32];
    #pragma unroll
    for (int p = 0; p < 32; p++)
        h[p] = pack_h2(v[2 * p], v[2 * p + 1]);
    unsigned char* row = g_WP +
        ((((size_t)sc * 2 + rank) * 2 + disp) * 128 + fr) * 128;
    int r7 = fr & 7;
    #pragma unroll
    for (int u = 0; u < 8; u++)
        *reinterpret_cast<uint4*>(row + ((u ^ r7) * 16)) =
            make_uint4(h[4 * u], h[4 * u + 1], h[4 * u + 2], h[4 * u + 3]);
}

// =====================================================================
// Main GEMM. grid=512 (clusters of 2), 544 threads.
// =====================================================================
__global__ void __launch_bounds__(NTHREADS, 1) __cluster_dims__(2, 1, 1)
spconv_kernel(const float* __restrict__ X, const float* __restrict__ W,
              const float* __restrict__ bias, float* __restrict__ out)
{
    extern __shared__ char smem[];
    const int tid = threadIdx.x;

#if HAS_TCGEN05
    const uint32_t sb = smem_u32(smem);
    const int wid = tid >> 5;
    const int lane = tid & 31;
    const uint32_t rank = ctarank();
    const int hw0 = (blockIdx.x >> 1) * 256;
    const int hwA0 = hw0 + (int)rank * 128;      // this CTA's A rows

    if (wid == 0) {
        asm volatile("tcgen05.alloc.cta_group::2.sync.aligned.shared::cta.b32 [%0], %1;"
                     :: "r"(sb), "r"(512u) : "memory");
        asm volatile("tcgen05.relinquish_alloc_permit.cta_group::2.sync.aligned;" ::: "memory");
    }
    if (tid == 0) {
        #pragma unroll
        for (int s = 0; s < NSTAGE; s++) {
            mbar_init(sb + MBAR_FULL(s), PRODS + 1);     // producers + expect_tx
            mbar_init(sb + MBAR_EMPTY(s), 1);            // multicast commit
            mbar_init(sb + MBAR_PEER(s), 1);             // rank1 cluster-arrive
        }
        mbar_init(sb + MBAR_DONE, 1);
    }
    if (tid < PRODS)
        reinterpret_cast<float*>(smem + BIAS_OFF)[tid] = bias[tid];
    __syncthreads();
    cluster_sync();                               // barriers visible cluster-wide
    uint32_t tmem;
    asm volatile("ld.shared.b32 %0, [%1];" : "=r"(tmem) : "r"(sb));

    if (tid < PRODS) {
        // ================= producer warps 0-15 =================
        uint64_t wg;
        asm("cvta.to.global.u64 %0, %1;" : "=l"(wg) : "l"((const void*)g_WP));
        wg += (uint64_t)rank * 32768;             // [sc][rank][disp][fr]

        const int xc = tid >> 5;                  // 0..15
        const int xq = tid & 31;                  // 0..31
        const float* xbase = X + hwA0 + xq * 4;

        float4 pf[4];
        #pragma unroll
        for (int i = 0; i < 4; i++)
            pf[i] = *reinterpret_cast<const float4*>(
                xbase + (size_t)(xc + 16 * i) * 65536);

        int pst = 0, pph = 1;
        for (int sc = 0; sc < NSC; sc++) {
            mbar_wait(sb + MBAR_EMPTY(pst), (uint32_t)pph);
            char* stg = smem + STAGE0 + pst * STAGE_SZ;
            const uint32_t stb = sb + STAGE0 + pst * STAGE_SZ;
            float* Xs = reinterpret_cast<float*>(smem + XS_OFF + (sc & 1) * 32768);

            if (tid == 0) {
                expect_tx(sb + MBAR_FULL(pst), 32768u);
                bulk_g2s(stb + B_OFF, wg + (uint64_t)sc * 65536ull, 32768u,
                         sb + MBAR_FULL(pst));
            }

            // drain prefetched fp32 X into staging [64 c][128 hw]
            #pragma unroll
            for (int i = 0; i < 4; i++)
                *reinterpret_cast<float4*>(&Xs[(xc + 16 * i) * 128 + xq * 4]) = pf[i];
            asm volatile("bar.sync 1, %0;" :: "r"(PRODS) : "memory");

            if (sc + 1 < NSC) {
                #pragma unroll
                for (int i = 0; i < 4; i++)
                    pf[i] = *reinterpret_cast<const float4*>(
                        xbase + (size_t)((sc + 1) * 64 + xc + 16 * i) * 65536);
            }

            // transpose + convert: thread owns (hw row, 16-c block), fp16 RN
            {
                const int hwl = tid & 127;
                const int h   = tid >> 7;         // c block: [16h, 16h+16)
                float v[16];
                #pragma unroll
                for (int q = 0; q < 16; q++)
                    v[q] = Xs[(h * 16 + q) * 128 + hwl];   // conflict-free
                uint32_t hv[8];
                #pragma unroll
                for (int p = 0; p < 8; p++)
                    hv[p] = pack_h2(v[2 * p], v[2 * p + 1]);
                unsigned char* rh = reinterpret_cast<unsigned char*>(stg + A_OFF) +
                                    (size_t)hwl * 128;
                const int r7 = hwl & 7;
                #pragma unroll
                for (int u = 0; u < 2; u++)
                    *reinterpret_cast<uint4*>(rh + (((2 * h + u) ^ r7) * 16)) =
                        make_uint4(hv[4 * u], hv[4 * u + 1],
                                   hv[4 * u + 2], hv[4 * u + 3]);
            }

            mbar_arrive(sb + MBAR_FULL(pst));
            if (++pst == NSTAGE) { pst = 0; pph ^= 1; }
        }
    } else if (tid == PRODS) {
        // ================= dedicated MMA thread (warp 16, lane 0) ==========
        int cst = 0, cph = 0;
        for (int sc = 0; sc < NSC; sc++) {
            const uint32_t stb = sb + STAGE0 + cst * STAGE_SZ;
            if (rank == 1) {
                mbar_wait(sb + MBAR_FULL(cst), (uint32_t)cph);
                asm volatile("fence.proxy.async.shared::cta;" ::: "memory");
                mbar_arrive_rank0(sb + MBAR_PEER(cst));
            } else {
                mbar_wait(sb + MBAR_FULL(cst), (uint32_t)cph);
                mbar_wait(sb + MBAR_PEER(cst), (uint32_t)cph);
                asm volatile("fence.proxy.async.shared::cta;" ::: "memory");
                uint64_t ad = sw128_desc_k(stb + A_OFF);
                // 8 dispatches: 4 k-steps x 2 f-halves
                #pragma unroll
                for (int k = 0; k < 4; k++) {
                    #pragma unroll
                    for (int disp = 0; disp < 2; disp++) {
                        uint64_t bd = sw128_desc_k(stb + B_OFF + disp * 16384) + k * 2;
                        mma_ss_cg2(tmem + disp * 256, ad + k * 2, bd,
                                   (sc == 0 && k == 0) ? 0u : 1u);
                    }
                }
                mma_commit_mc2(sb + MBAR_EMPTY(cst));    // flips both CTAs
                if (sc == NSC - 1) mma_commit_mc2(sb + MBAR_DONE);
            }
            if (++cst == NSTAGE) { cst = 0; cph ^= 1; }
        }
    }

    // ---- epilogue: producer warps read 128 hw rows x 512 f cols ----
    if (wid < 16) {
        mbar_wait(sb + MBAR_DONE, 0u);
        asm volatile("tcgen05.fence::after_thread_sync;" ::: "memory");

        const float* bias_s = reinterpret_cast<const float*>(smem + BIAS_OFF);
        const int sub = wid & 3;                 // TMEM subpartition
        const int cg  = wid >> 2;                // column group (0..3)
        const int hw  = hwA0 + sub * 32 + lane;
        #pragma unroll
        for (int cb = 0; cb < 4; cb++) {
            uint32_t col = (uint32_t)(cg * 128 + cb * 32);  // col == f (linear)
            uint32_t r[32];
            ldtm_x32(r, tmem + col);
            asm volatile("tcgen05.wait::ld.sync.aligned;" ::: "memory");
            float* op = out + (size_t)col * 65536 + hw;
            #pragma unroll
            for (int q = 0; q < 32; q++) {
                float v = __uint_as_float(r[q]) + bias_s[col + q];
                op[(size_t)q * 65536] = fmaxf(v, 0.0f);
            }
        }
    }

    __syncthreads();
    cluster_sync();                               // both CTAs done reading TMEM
    if (wid == 0) {
        asm volatile("tcgen05.dealloc.cta_group::2.sync.aligned.b32 %0, %1;"
                     :: "r"(tmem), "r"(512u));
    }
    cluster_sync();

#else
    // ========= FFMA fallback (plain pass; never executes on GB300) =========
    if (tid < 512) {
        float* Xsf = reinterpret_cast<float*>(smem);            // [32][128]
        float* Wsf = reinterpret_cast<float*>(smem + 16384);    // [512][32]
        const int hw0f = (int)blockIdx.x * 128;
        const int tx = tid & 15, ty = tid >> 4;
        const int hw_l = tx * 8, f_l = ty * 16;
        float acc[16][8];
        #pragma unroll
        for (int i = 0; i < 16; i++)
            #pragma unroll
            for (int j = 0; j < 8; j++) acc[i][j] = 0.0f;
        for (int ch = 0; ch < 16; ch++) {
            const int c0 = ch * 32;
            #pragma unroll
            for (int i = 0; i < 2; i++) {
                int l = tid + 512 * i, row = l >> 5, c4 = l & 31;
                *reinterpret_cast<float4*>(&Xsf[row * 128 + c4 * 4]) =
                    *reinterpret_cast<const float4*>(
                        &X[(size_t)(c0 + row) * 65536 + hw0f + c4 * 4]);
            }
            #pragma unroll
            for (int i = 0; i < 8; i++) {
                int l = tid + 512 * i, row = l >> 3, c4 = l & 7;
                *reinterpret_cast<float4*>(&Wsf[row * 32 + c4 * 4]) =
                    *reinterpret_cast<const float4*>(
                        &W[(size_t)row * 512 + c0 + c4 * 4]);
            }
            __syncthreads();
            #pragma unroll 4
            for (int c = 0; c < 32; c++) {
                float xv[8];
                *reinterpret_cast<float4*>(xv) =
                    *reinterpret_cast<float4*>(&Xsf[c * 128 + hw_l]);
                *reinterpret_cast<float4*>(xv + 4) =
                    *reinterpret_cast<float4*>(&Xsf[c * 128 + hw_l + 4]);
                #pragma unroll
                for (int i = 0; i < 16; i++) {
                    float wv = Wsf[(f_l + i) * 32 + c];
                    #pragma unroll
                    for (int j = 0; j < 8; j++) acc[i][j] += wv * xv[j];
                }
            }
            __syncthreads();
        }
        #pragma unroll
        for (int i = 0; i < 16; i++) {
            float b = bias[f_l + i];
            float* op = out + (size_t)(f_l + i) * 65536 + hw0f + hw_l;
            #pragma unroll
            for (int j = 0; j < 8; j++)
                op[j] = fmaxf(acc[i][j] + b, 0.0f);
        }
    } else {
        for (int it = 0; it < 32; it++) __syncthreads();
    }
#endif
}

extern "C" void kernel_launch(void* const* d_in, const int* in_sizes, int n_in,
                              void* d_out, int out_size) {
    const float* X = (const float*)d_in[0];      // [1,512,256,256]
    const float* W = (const float*)d_in[1];      // [512,512] (already masked)
    const float* bias = (const float*)d_in[n_in - 1];
    for (int i = 1; i < n_in; i++)
        if (in_sizes[i] == 512) { bias = (const float*)d_in[i]; break; }
    float* out = (float*)d_out;

    static bool attr_done = false;
    if (!attr_done) {
        cudaFuncSetAttribute(spconv_kernel,
                             cudaFuncAttributeMaxDynamicSharedMemorySize, SMEM_TOTAL);
        attr_done = true;
    }

    wprep_kernel<<<16, 256>>>(W);
    spconv_kernel<<<512, NTHREADS, SMEM_TOTAL>>>(X, W, bias, out);
}